// round 5
// baseline (speedup 1.0000x reference)
#include <cuda_runtime.h>
#include <cuda_bf16.h>
#include <cstdint>

// norm_conv via mma.sync bf16-split implicit GEMM.
// out = ((im2col(a)-mean)/std) @ W == (conv3x3(a,W) - mean*colsum(W)) * rstd
// Per CTA: 128-pixel tile (4 rows) of one batch, 8 warps x (16 pix x 64 out).
// Input pre-split into bf16 hi/lo planes (pixel-major) once; 9 taps of
// K=64 GEMM accumulation, B via ldmatrix, 3-term bf16 split products.

#define SM_WSUM 0                      // 64 f
#define SM_MEAN 256                    // 128 f
#define SM_RSTD 768                    // 128 f
#define SM_S1   1280                   // 204 f
#define SM_S2   2096                   // 204 f
#define SM_B0   3072                   // 2 x B_BYTES double buffer
#define B_BYTES 18432                  // per tap: hi[64][72] + lo[64][72] bf16
#define SM_HI   (SM_B0 + 2 * B_BYTES)  // 39936: [204 pix][36 words] bf16x2
#define SM_LO   (SM_HI + 204 * 36 * 4) // 69312
#define SMEM_TOTAL (SM_LO + 204 * 36 * 4)   // 98688 bytes -> 2 CTAs/SM
#define IN_W    36                     // u32 words per pixel row (64ch + pad)

__device__ float g_wsum[64];
__device__ __align__(16) __nv_bfloat16 g_wtp[9 * 2 * 64 * 72]; // [tap][hl][o][k]

__device__ __forceinline__ int refl(int i) {
    i = (i < 0) ? -i : i;
    return (i >= 32) ? 62 - i : i;
}

#define CVT_BF16X2(res, f0, f1) \
    asm("cvt.rn.satfinite.bf16x2.f32 %0, %1, %2;" : "=r"(res) : "f"(f1), "f"(f0))

#define CP_ASYNC16(dst, src) \
    asm volatile("cp.async.cg.shared.global [%0], [%1], 16;" \
                 :: "r"(dst), "l"(src) : "memory")
#define CP_COMMIT() asm volatile("cp.async.commit_group;" ::: "memory")
#define CP_WAIT(n)  asm volatile("cp.async.wait_group %0;" :: "n"(n) : "memory")

#define MMA16816(c, a0, a1, a2, a3, b0, b1) \
    asm volatile("mma.sync.aligned.m16n8k16.row.col.f32.bf16.bf16.f32 " \
        "{%0,%1,%2,%3}, {%4,%5,%6,%7}, {%8,%9}, {%0,%1,%2,%3};" \
        : "+f"((c)[0]), "+f"((c)[1]), "+f"((c)[2]), "+f"((c)[3]) \
        : "r"(a0), "r"(a1), "r"(a2), "r"(a3), "r"(b0), "r"(b1))

#define LDSM_X4(r0, r1, r2, r3, addr) \
    asm volatile("ldmatrix.sync.aligned.m8n8.x4.shared.b16 {%0,%1,%2,%3}, [%4];" \
        : "=r"(r0), "=r"(r1), "=r"(r2), "=r"(r3) : "r"(addr))

// blocks 0..323: bf16 hi/lo split of W into g_wtp[tap][hl][o][k] (k padded 72).
// block 324: column sums of W into g_wsum.
__global__ void prep_kernel(const float* __restrict__ w) {
    if (blockIdx.x == 324) {
        int t = threadIdx.x;
        int o = t >> 2, q = t & 3;
        float s = 0.f;
        for (int p = q; p < 576; p += 4) s += w[p * 64 + o];
        s += __shfl_xor_sync(0xffffffffu, s, 1);
        s += __shfl_xor_sync(0xffffffffu, s, 2);
        if (q == 0) g_wsum[o] = s;
        return;
    }
    int idx = blockIdx.x * 256 + threadIdx.x;   // < 82944 == 9*2*64*72
    int k = idx % 72;
    int rest = idx / 72;
    int o = rest & 63;
    rest >>= 6;
    int hl = rest & 1, tap = rest >> 1;
    __nv_bfloat16 v = __float2bfloat16(0.f);
    if (k < 64) {
        float f = w[(k * 9 + tap) * 64 + o];
        __nv_bfloat16 hi = __float2bfloat16(f);
        v = (hl == 0) ? hi : __float2bfloat16(f - __bfloat162float(hi));
    }
    g_wtp[idx] = v;
}

__global__ __launch_bounds__(256, 2)
void conv_mma_kernel(const float* __restrict__ a, float* __restrict__ out) {
    extern __shared__ char smem[];
    float* smf = (float*)smem;
    uint32_t sb;
    asm("{ .reg .u64 t; cvta.to.shared.u64 t, %1; cvt.u32.u64 %0, t; }"
        : "=r"(sb) : "l"(smem));

    const int t = threadIdx.x;
    const int wrp = t >> 5, l = t & 31;
    const int b = blockIdx.x >> 3;
    const int row0 = (blockIdx.x & 7) << 2;
    const float* A = a + (size_t)b * 65536;

    // prefetch B tap0 into buffer 0
    {
        const char* src = (const char*)g_wtp;
        for (int i = t; i < B_BYTES / 16; i += 256)
            CP_ASYNC16(sb + SM_B0 + i * 16, __cvta_generic_to_global(src + i * 16));
        CP_COMMIT();
    }
    if (t < 64) smf[SM_WSUM / 4 + t] = g_wsum[t];

    // stage + bf16-split input tile into pixel-major hi/lo planes.
    // word (pix, cw) holds channels (2cw, 2cw+1) of pixel pix.
    {
        uint32_t* hip = (uint32_t*)(smem + SM_HI);
        uint32_t* lop = (uint32_t*)(smem + SM_LO);
        for (int idx = t; idx < 32 * 204; idx += 256) {
            int cw = idx / 204, pix = idx - cw * 204;
            int ry = pix / 34, cx = pix - ry * 34;
            int py = refl(row0 - 1 + ry), px = refl(cx - 1);
            const float* p = A + (2 * cw) * 1024 + py * 32 + px;
            float f0 = p[0], f1 = p[1024];
            uint32_t hx; CVT_BF16X2(hx, f0, f1);
            float h0 = __uint_as_float(hx << 16);
            float h1 = __uint_as_float(hx & 0xffff0000u);
            uint32_t lx; CVT_BF16X2(lx, f0 - h0, f1 - h1);
            hip[pix * IN_W + cw] = hx;
            lop[pix * IN_W + cw] = lx;
        }
    }
    __syncthreads();

    // stats: channel reduce (reconstruct v = hi + lo), then 3x3 box sums
    if (t < 204) {
        const uint32_t* hip = (const uint32_t*)(smem + SM_HI) + t * IN_W;
        const uint32_t* lop = (const uint32_t*)(smem + SM_LO) + t * IN_W;
        float s1 = 0.f, s2 = 0.f;
        #pragma unroll 8
        for (int w = 0; w < 32; ++w) {
            uint32_t hx = hip[w], lx = lop[w];
            float f0 = __uint_as_float(hx << 16) + __uint_as_float(lx << 16);
            float f1 = __uint_as_float(hx & 0xffff0000u) +
                       __uint_as_float(lx & 0xffff0000u);
            s1 += f0 + f1;
            s2 += f0 * f0 + f1 * f1;
        }
        smf[SM_S1 / 4 + t] = s1;
        smf[SM_S2 / 4 + t] = s2;
    }
    __syncthreads();
    if (t < 128) {
        int r = t >> 5, x = t & 31;
        float s1 = 0.f, s2 = 0.f;
        #pragma unroll
        for (int dr = 0; dr < 3; ++dr)
            #pragma unroll
            for (int dc = 0; dc < 3; ++dc) {
                int i = (r + dr) * 34 + x + dc;
                s1 += smf[SM_S1 / 4 + i];
                s2 += smf[SM_S2 / 4 + i];
            }
        float mean = s1 * (1.f / 576.f);
        float var  = (s2 - s1 * s1 * (1.f / 576.f)) * (1.f / 575.f);
        smf[SM_MEAN / 4 + t] = mean;
        smf[SM_RSTD / 4 + t] = rsqrtf(fmaxf(var, 1e-30f));
    }

    // warp tile: pixels [wrp*16, wrp*16+16), all 64 out channels
    const int g = l >> 2, tg = l & 3;
    const int p0 = wrp * 16 + g, p1 = p0 + 8;
    const int r0g = p0 >> 5, x0g = p0 & 31;
    const int r1g = p1 >> 5, x1g = p1 & 31;

    // ldmatrix lane offset: tile = l>>3 -> (nc-sub = tile>>1, half = tile&1)
    // row bytes: ((tile>>1)*8 + (l&7))*144 + (tile&1)*16, + j*2304 + kc*32
    const uint32_t lds_lane =
        (uint32_t)((((l >> 4) & 1) * 8 + (l & 7)) * 144 + ((l >> 3) & 1) * 16);

    float acc[8][4];
    #pragma unroll
    for (int i = 0; i < 8; ++i)
        #pragma unroll
        for (int j = 0; j < 4; ++j) acc[i][j] = 0.f;

    int buf = 0;
    for (int tap = 0; tap < 9; ++tap) {
        if (tap < 8) {
            const char* src = (const char*)g_wtp + (size_t)(tap + 1) * B_BYTES;
            uint32_t dst = sb + SM_B0 + (buf ^ 1) * B_BYTES;
            for (int i = t; i < B_BYTES / 16; i += 256)
                CP_ASYNC16(dst + i * 16, __cvta_generic_to_global(src + i * 16));
            CP_COMMIT();
            CP_WAIT(1);
        } else {
            CP_WAIT(0);
        }
        __syncthreads();

        const int dy = tap / 3, dx = tap - dy * 3;
        const int base0 = ((r0g + dy) * 34 + x0g + dx) * IN_W;
        const int base1 = ((r1g + dy) * 34 + x1g + dx) * IN_W;
        const uint32_t* hip = (const uint32_t*)(smem + SM_HI);
        const uint32_t* lop = (const uint32_t*)(smem + SM_LO);
        const uint32_t bhb = sb + SM_B0 + buf * B_BYTES + lds_lane;
        const uint32_t blb = bhb + 9216;

        #pragma unroll
        for (int kc = 0; kc < 4; ++kc) {
            const int wo = kc * 8 + tg;
            uint32_t ah0 = hip[base0 + wo],     ah1 = hip[base1 + wo];
            uint32_t ah2 = hip[base0 + wo + 4], ah3 = hip[base1 + wo + 4];
            uint32_t al0 = lop[base0 + wo],     al1 = lop[base1 + wo];
            uint32_t al2 = lop[base0 + wo + 4], al3 = lop[base1 + wo + 4];

            uint32_t bh[16], bl[16];
            #pragma unroll
            for (int j = 0; j < 4; ++j) {
                uint32_t addr = j * 2304u + kc * 32u;
                LDSM_X4(bh[4 * j], bh[4 * j + 1], bh[4 * j + 2], bh[4 * j + 3],
                        bhb + addr);
                LDSM_X4(bl[4 * j], bl[4 * j + 1], bl[4 * j + 2], bl[4 * j + 3],
                        blb + addr);
            }
            #pragma unroll
            for (int nc = 0; nc < 8; ++nc) {
                MMA16816(acc[nc], ah0, ah1, ah2, ah3, bh[nc * 2], bh[nc * 2 + 1]);
                MMA16816(acc[nc], ah0, ah1, ah2, ah3, bl[nc * 2], bl[nc * 2 + 1]);
                MMA16816(acc[nc], al0, al1, al2, al3, bh[nc * 2], bh[nc * 2 + 1]);
            }
        }
        buf ^= 1;
        __syncthreads();
    }

    // epilogue: (acc - mean*wsum) * rstd
    const int offp0 = row0 * 32 + p0;
    const int offp1 = row0 * 32 + p1;
    const float mean0 = smf[SM_MEAN / 4 + p0], rstd0 = smf[SM_RSTD / 4 + p0];
    const float mean1 = smf[SM_MEAN / 4 + p1], rstd1 = smf[SM_RSTD / 4 + p1];
    float* ob = out + (size_t)b * 65536;
    #pragma unroll
    for (int nc = 0; nc < 8; ++nc) {
        const int o0 = nc * 8 + tg * 2;
        const float ws0 = smf[SM_WSUM / 4 + o0];
        const float ws1 = smf[SM_WSUM / 4 + o0 + 1];
        ob[(size_t)o0 * 1024 + offp0]       = (acc[nc][0] - mean0 * ws0) * rstd0;
        ob[(size_t)(o0 + 1) * 1024 + offp0] = (acc[nc][1] - mean0 * ws1) * rstd0;
        ob[(size_t)o0 * 1024 + offp1]       = (acc[nc][2] - mean1 * ws0) * rstd1;
        ob[(size_t)(o0 + 1) * 1024 + offp1] = (acc[nc][3] - mean1 * ws1) * rstd1;
    }
}

extern "C" void kernel_launch(void* const* d_in, const int* in_sizes, int n_in,
                              void* d_out, int out_size) {
    const float* a = (const float*)d_in[0];   // [256,64,32,32]
    const float* w = (const float*)d_in[1];   // [576,64]
    float* out = (float*)d_out;

    cudaFuncSetAttribute(conv_mma_kernel,
                         cudaFuncAttributeMaxDynamicSharedMemorySize, SMEM_TOTAL);

    prep_kernel<<<325, 256>>>(w);
    conv_mma_kernel<<<2048, 256, SMEM_TOTAL>>>(a, out);
}

// round 6
// speedup vs baseline: 1.6724x; 1.6724x over previous
#include <cuda_runtime.h>
#include <cuda_bf16.h>
#include <cstdint>

// norm_conv via mma.sync bf16-split implicit GEMM.
// out = ((im2col(a)-mean)/std) @ W == (conv3x3(a,W) - mean*colsum(W)) * rstd
// Per CTA: 128-pixel tile (4 rows) of one batch, 8 warps.
// Warp = 32 pixels (one image row, two m16 tiles) x 32 out channels (half).
// Input pre-split once into bf16 hi/lo pixel-major planes; 9 taps of K=64
// GEMM accumulation, B via ldmatrix, 3-term bf16 split products.

#define SM_WSUM 0                      // 64 f
#define SM_MEAN 256                    // 128 f
#define SM_RSTD 768                    // 128 f
#define SM_S1   1280                   // 204 f
#define SM_S2   2096                   // 204 f
#define SM_B0   3072                   // 2 x B_BYTES double buffer
#define B_BYTES 18432                  // per tap: hi[64][72] + lo[64][72] bf16
#define SM_HI   (SM_B0 + 2 * B_BYTES)  // 39936: [204 pix][36 words] bf16x2
#define SM_LO   (SM_HI + 204 * 36 * 4) // 69312
#define SMEM_TOTAL (SM_LO + 204 * 36 * 4)   // 98688 bytes -> 2 CTAs/SM
#define IN_W    36                     // u32 words per pixel (64ch + pad)

__device__ float g_wsum[64];
__device__ __align__(16) __nv_bfloat16 g_wtp[9 * 2 * 64 * 72]; // [tap][hl][o][k]

__device__ __forceinline__ int refl(int i) {
    i = (i < 0) ? -i : i;
    return (i >= 32) ? 62 - i : i;
}

#define CVT_BF16X2(res, f0, f1) \
    asm("cvt.rn.satfinite.bf16x2.f32 %0, %1, %2;" : "=r"(res) : "f"(f1), "f"(f0))

#define CP_ASYNC16(dst, src) \
    asm volatile("cp.async.cg.shared.global [%0], [%1], 16;" \
                 :: "r"(dst), "l"(src) : "memory")
#define CP_COMMIT() asm volatile("cp.async.commit_group;" ::: "memory")
#define CP_WAIT(n)  asm volatile("cp.async.wait_group %0;" :: "n"(n) : "memory")

#define MMA16816(c, a0, a1, a2, a3, b0, b1) \
    asm volatile("mma.sync.aligned.m16n8k16.row.col.f32.bf16.bf16.f32 " \
        "{%0,%1,%2,%3}, {%4,%5,%6,%7}, {%8,%9}, {%0,%1,%2,%3};" \
        : "+f"((c)[0]), "+f"((c)[1]), "+f"((c)[2]), "+f"((c)[3]) \
        : "r"(a0), "r"(a1), "r"(a2), "r"(a3), "r"(b0), "r"(b1))

#define LDSM_X4(r0, r1, r2, r3, addr) \
    asm volatile("ldmatrix.sync.aligned.m8n8.x4.shared.b16 {%0,%1,%2,%3}, [%4];" \
        : "=r"(r0), "=r"(r1), "=r"(r2), "=r"(r3) : "r"(addr))

// blocks 0..323: bf16 hi/lo split of W into g_wtp[tap][hl][o][k] (k padded 72).
// block 324: column sums of W into g_wsum.
__global__ void prep_kernel(const float* __restrict__ w) {
    if (blockIdx.x == 324) {
        int t = threadIdx.x;
        int o = t >> 2, q = t & 3;
        float s = 0.f;
        for (int p = q; p < 576; p += 4) s += w[p * 64 + o];
        s += __shfl_xor_sync(0xffffffffu, s, 1);
        s += __shfl_xor_sync(0xffffffffu, s, 2);
        if (q == 0) g_wsum[o] = s;
        return;
    }
    int idx = blockIdx.x * 256 + threadIdx.x;   // < 82944 == 9*2*64*72
    int k = idx % 72;
    int rest = idx / 72;
    int o = rest & 63;
    rest >>= 6;
    int hl = rest & 1, tap = rest >> 1;
    __nv_bfloat16 v = __float2bfloat16(0.f);
    if (k < 64) {
        float f = w[(k * 9 + tap) * 64 + o];
        __nv_bfloat16 hi = __float2bfloat16(f);
        v = (hl == 0) ? hi : __float2bfloat16(f - __bfloat162float(hi));
    }
    g_wtp[idx] = v;
}

__global__ __launch_bounds__(256, 2)
void conv_mma_kernel(const float* __restrict__ a, float* __restrict__ out) {
    extern __shared__ char smem[];
    float* smf = (float*)smem;
    uint32_t sb;
    asm("{ .reg .u64 t; cvta.to.shared.u64 t, %1; cvt.u32.u64 %0, t; }"
        : "=r"(sb) : "l"(smem));

    const int t = threadIdx.x;
    const int wrp = t >> 5, l = t & 31;
    const int b = blockIdx.x >> 3;
    const int row0 = (blockIdx.x & 7) << 2;
    const float* A = a + (size_t)b * 65536;

    // prefetch B tap0 into buffer 0
    {
        const char* src = (const char*)g_wtp;
        for (int i = t; i < B_BYTES / 16; i += 256)
            CP_ASYNC16(sb + SM_B0 + i * 16, __cvta_generic_to_global(src + i * 16));
        CP_COMMIT();
    }
    if (t < 64) smf[SM_WSUM / 4 + t] = g_wsum[t];

    // stage + bf16-split input tile into pixel-major hi/lo planes.
    // word (pix, cw) holds channels (2cw, 2cw+1) of pixel pix.
    {
        uint32_t* hip = (uint32_t*)(smem + SM_HI);
        uint32_t* lop = (uint32_t*)(smem + SM_LO);
        for (int idx = t; idx < 32 * 204; idx += 256) {
            int cw = idx / 204, pix = idx - cw * 204;
            int ry = pix / 34, cx = pix - ry * 34;
            int py = refl(row0 - 1 + ry), px = refl(cx - 1);
            const float* p = A + (2 * cw) * 1024 + py * 32 + px;
            float f0 = p[0], f1 = p[1024];
            uint32_t hx; CVT_BF16X2(hx, f0, f1);
            float h0 = __uint_as_float(hx << 16);
            float h1 = __uint_as_float(hx & 0xffff0000u);
            uint32_t lx; CVT_BF16X2(lx, f0 - h0, f1 - h1);
            hip[pix * IN_W + cw] = hx;
            lop[pix * IN_W + cw] = lx;
        }
    }
    __syncthreads();

    // stats: channel reduce (reconstruct v = hi + lo), then 3x3 box sums
    if (t < 204) {
        const uint32_t* hip = (const uint32_t*)(smem + SM_HI) + t * IN_W;
        const uint32_t* lop = (const uint32_t*)(smem + SM_LO) + t * IN_W;
        float s1 = 0.f, s2 = 0.f;
        #pragma unroll 8
        for (int w = 0; w < 32; ++w) {
            uint32_t hx = hip[w], lx = lop[w];
            float f0 = __uint_as_float(hx << 16) + __uint_as_float(lx << 16);
            float f1 = __uint_as_float(hx & 0xffff0000u) +
                       __uint_as_float(lx & 0xffff0000u);
            s1 += f0 + f1;
            s2 += f0 * f0 + f1 * f1;
        }
        smf[SM_S1 / 4 + t] = s1;
        smf[SM_S2 / 4 + t] = s2;
    }
    __syncthreads();
    if (t < 128) {
        int r = t >> 5, x = t & 31;
        float s1 = 0.f, s2 = 0.f;
        #pragma unroll
        for (int dr = 0; dr < 3; ++dr)
            #pragma unroll
            for (int dc = 0; dc < 3; ++dc) {
                int i = (r + dr) * 34 + x + dc;
                s1 += smf[SM_S1 / 4 + i];
                s2 += smf[SM_S2 / 4 + i];
            }
        float mean = s1 * (1.f / 576.f);
        float var  = (s2 - s1 * s1 * (1.f / 576.f)) * (1.f / 575.f);
        smf[SM_MEAN / 4 + t] = mean;
        smf[SM_RSTD / 4 + t] = rsqrtf(fmaxf(var, 1e-30f));
    }

    // warp tile: image row (wrp>>1), 32 pixels (2 m16 tiles), out half wrp&1
    const int g = l >> 2, tg = l & 3;
    const int row = wrp >> 1, h = wrp & 1;

    // ldmatrix lane offset within a 16-n j'-group (proven mapping)
    const uint32_t lds_lane =
        (uint32_t)((((l >> 4) & 1) * 8 + (l & 7)) * 144 + ((l >> 3) & 1) * 16);

    float acc[2][4][4];
    #pragma unroll
    for (int i = 0; i < 2; ++i)
        #pragma unroll
        for (int j = 0; j < 4; ++j)
            #pragma unroll
            for (int q = 0; q < 4; ++q) acc[i][j][q] = 0.f;

    const uint32_t* hip = (const uint32_t*)(smem + SM_HI);
    const uint32_t* lop = (const uint32_t*)(smem + SM_LO);

    int buf = 0;
    for (int tap = 0; tap < 9; ++tap) {
        CP_WAIT(0);
        __syncthreads();
        if (tap < 8) {
            const char* src = (const char*)g_wtp + (size_t)(tap + 1) * B_BYTES;
            uint32_t dst = sb + SM_B0 + (buf ^ 1) * B_BYTES;
            for (int i = t; i < B_BYTES / 16; i += 256)
                CP_ASYNC16(dst + i * 16, __cvta_generic_to_global(src + i * 16));
            CP_COMMIT();
        }

        const int dy = tap / 3, dx = tap - dy * 3;
        const int base0 = ((row + dy) * 34 + g + dx) * IN_W;   // tile0, pixel x=g
        const int base1 = base0 + 16 * IN_W;                   // tile1, x=16+g
        const uint32_t bhb = sb + SM_B0 + buf * B_BYTES + lds_lane + h * 2 * 2304;
        const uint32_t blb = bhb + 9216;

        #pragma unroll
        for (int kc = 0; kc < 4; ++kc) {
            const int wo = kc * 8 + tg;
            uint32_t ah00 = hip[base0 + wo],            ah01 = hip[base0 + 8 * IN_W + wo];
            uint32_t ah02 = hip[base0 + wo + 4],        ah03 = hip[base0 + 8 * IN_W + wo + 4];
            uint32_t al00 = lop[base0 + wo],            al01 = lop[base0 + 8 * IN_W + wo];
            uint32_t al02 = lop[base0 + wo + 4],        al03 = lop[base0 + 8 * IN_W + wo + 4];
            uint32_t ah10 = hip[base1 + wo],            ah11 = hip[base1 + 8 * IN_W + wo];
            uint32_t ah12 = hip[base1 + wo + 4],        ah13 = hip[base1 + 8 * IN_W + wo + 4];
            uint32_t al10 = lop[base1 + wo],            al11 = lop[base1 + 8 * IN_W + wo];
            uint32_t al12 = lop[base1 + wo + 4],        al13 = lop[base1 + 8 * IN_W + wo + 4];

            #pragma unroll
            for (int j = 0; j < 2; ++j) {
                uint32_t addr = (uint32_t)(j * 2304 + kc * 32);
                uint32_t bh0, bh1, bh2, bh3, bl0, bl1, bl2, bl3;
                LDSM_X4(bh0, bh1, bh2, bh3, bhb + addr);
                LDSM_X4(bl0, bl1, bl2, bl3, blb + addr);
                // nc = 2j (frags bh0,bh1 / bl0,bl1)
                MMA16816(acc[0][2 * j], ah00, ah01, ah02, ah03, bh0, bh1);
                MMA16816(acc[1][2 * j], ah10, ah11, ah12, ah13, bh0, bh1);
                MMA16816(acc[0][2 * j], ah00, ah01, ah02, ah03, bl0, bl1);
                MMA16816(acc[1][2 * j], ah10, ah11, ah12, ah13, bl0, bl1);
                MMA16816(acc[0][2 * j], al00, al01, al02, al03, bh0, bh1);
                MMA16816(acc[1][2 * j], al10, al11, al12, al13, bh0, bh1);
                // nc = 2j+1 (frags bh2,bh3 / bl2,bl3)
                MMA16816(acc[0][2 * j + 1], ah00, ah01, ah02, ah03, bh2, bh3);
                MMA16816(acc[1][2 * j + 1], ah10, ah11, ah12, ah13, bh2, bh3);
                MMA16816(acc[0][2 * j + 1], ah00, ah01, ah02, ah03, bl2, bl3);
                MMA16816(acc[1][2 * j + 1], ah10, ah11, ah12, ah13, bl2, bl3);
                MMA16816(acc[0][2 * j + 1], al00, al01, al02, al03, bh2, bh3);
                MMA16816(acc[1][2 * j + 1], al10, al11, al12, al13, bh2, bh3);
            }
        }
        buf ^= 1;
    }

    // epilogue: (acc - mean*wsum) * rstd
    float* ob = out + (size_t)b * 65536 + (size_t)(row0 + row) * 32;
    #pragma unroll
    for (int t2 = 0; t2 < 2; ++t2) {
        const int x0 = t2 * 16 + g;
        const int pp = row * 32 + x0;
        const float mean0 = smf[SM_MEAN / 4 + pp],     rstd0 = smf[SM_RSTD / 4 + pp];
        const float mean1 = smf[SM_MEAN / 4 + pp + 8], rstd1 = smf[SM_RSTD / 4 + pp + 8];
        #pragma unroll
        for (int nc = 0; nc < 4; ++nc) {
            const int o0 = h * 32 + nc * 8 + tg * 2;
            const float ws0 = smf[SM_WSUM / 4 + o0];
            const float ws1 = smf[SM_WSUM / 4 + o0 + 1];
            ob[(size_t)o0 * 1024 + x0]           = (acc[t2][nc][0] - mean0 * ws0) * rstd0;
            ob[(size_t)(o0 + 1) * 1024 + x0]     = (acc[t2][nc][1] - mean0 * ws1) * rstd0;
            ob[(size_t)o0 * 1024 + x0 + 8]       = (acc[t2][nc][2] - mean1 * ws0) * rstd1;
            ob[(size_t)(o0 + 1) * 1024 + x0 + 8] = (acc[t2][nc][3] - mean1 * ws1) * rstd1;
        }
    }
}

extern "C" void kernel_launch(void* const* d_in, const int* in_sizes, int n_in,
                              void* d_out, int out_size) {
    const float* a = (const float*)d_in[0];   // [256,64,32,32]
    const float* w = (const float*)d_in[1];   // [576,64]
    float* out = (float*)d_out;

    cudaFuncSetAttribute(conv_mma_kernel,
                         cudaFuncAttributeMaxDynamicSharedMemorySize, SMEM_TOTAL);

    prep_kernel<<<325, 256>>>(w);
    conv_mma_kernel<<<2048, 256, SMEM_TOTAL>>>(a, out);
}